// round 7
// baseline (speedup 1.0000x reference)
#include <cuda_runtime.h>
#include <cstdint>

// Degenerate BiLSTM: h=c=0 => only emb[:,S-1] (fwd) and emb[:,0] (bwd) matter;
// f-gate dead; Whf/Whb unused.  B=128, S=2048, EMB=128, HID=256, OUT=32.
//
// Grid 144 (single wave on 148 SMs) = 128 workers + 16 head blocks.
// Worker: W tile via cp.async.bulk; x gathered into [lb][e] rows padded to 132
// words (conflict-free LDS.128); GEMV with fma.rn.f32x2 (2 h x 3 gates/thread);
// hy -> g_hy[h][b]; release via fence+atomic.
// Head (4 per bg, 8 batches each): stages Why[o][k] (260-word rows, CF LDS.128)
// DURING the worker phase, epoch-safe spin on wcnt, hy stage, vectorized GEMV,
// 32-wide log-softmax.

#define NB_B   128
#define NB_S   2048
#define NB_EMB 128
#define NB_HID 256
#define NB_OUT 32

__device__ unsigned int g_wcnt[4];            // +32 per launch per bg (workers)
__device__ unsigned int g_hcnt[4];            // +4  per launch per bg (heads)
__device__ float        g_hy[NB_HID * NB_B];  // [h][b]

// dynamic smem byte offsets (worker / head overlays)
#define SM_XS    0              // worker: xs 8448 floats  | head: Why_s2 8320 floats
#define SM_WSM   33792          // worker: W tile 24576 B  | head: hy_s 8*260 floats
#define SM_RED   58368          // worker: 8*33 floats
#define SM_TOK   59424          // 64 ints
#define SM_MBAR  59680          // 8 B
#define SMEM_BYTES 59904

__device__ __forceinline__ float fsigm(float x) {
    return __fdividef(1.0f, 1.0f + __expf(-x));
}
__device__ __forceinline__ float ftanh(float x) {
    float r; asm("tanh.approx.f32 %0, %1;" : "=f"(r) : "f"(x)); return r;
}
__device__ __forceinline__ unsigned int smem_u32(const void* p) {
    unsigned int a;
    asm("{ .reg .u64 t; cvta.to.shared.u64 t, %1; cvt.u32.u64 %0, t; }"
        : "=r"(a) : "l"(p));
    return a;
}
__device__ __forceinline__ unsigned long long fma2(
    unsigned long long a, unsigned long long b, unsigned long long c) {
    unsigned long long d;
    asm("fma.rn.f32x2 %0, %1, %2, %3;" : "=l"(d) : "l"(a), "l"(b), "l"(c));
    return d;
}
__device__ __forceinline__ void lds_v2b64(unsigned int a,
                                          unsigned long long& x,
                                          unsigned long long& y) {
    asm volatile("ld.shared.v2.b64 {%0, %1}, [%2];" : "=l"(x), "=l"(y) : "r"(a));
}
__device__ __forceinline__ float acc_sum(unsigned long long v) {
    return __uint_as_float((unsigned int)v) + __uint_as_float((unsigned int)(v >> 32));
}

__device__ __forceinline__ void mbar_wait0(unsigned int mbar) {
    unsigned int done;
    asm volatile(
        "{\n\t.reg .pred p;\n\t"
        "mbarrier.try_wait.parity.acquire.cta.shared::cta.b64 p, [%1], 0;\n\t"
        "selp.b32 %0, 1, 0, p;\n\t}"
        : "=r"(done) : "r"(mbar) : "memory");
    if (!done) {
        asm volatile(
            "{\n\t.reg .pred P1;\n\t"
            "WL_%=:\n\t"
            "mbarrier.try_wait.parity.acquire.cta.shared::cta.b64 P1, [%0], 0, 0x989680;\n\t"
            "@P1 bra.uni WD_%=;\n\t"
            "bra.uni WL_%=;\n\t"
            "WD_%=:\n\t}"
            :: "r"(mbar) : "memory");
    }
}

__global__ void __launch_bounds__(256, 1) bilstm_kernel(
    const int*   __restrict__ inputs,   // [B, S]
    const float* __restrict__ weight,   // [VOCAB, EMB]
    const float* __restrict__ Wxf,      // [1024, 128]
    const float* __restrict__ bxf,
    const float* __restrict__ bhf,
    const float* __restrict__ Wxb,
    const float* __restrict__ bxb,
    const float* __restrict__ bhb,
    const float* __restrict__ Why,      // [32, 256]
    const float* __restrict__ by,       // [32]
    float*       __restrict__ out)      // [B, 32]
{
    extern __shared__ char dsm[];
    const int tid = threadIdx.x;
    const int bid = blockIdx.x;

    if (bid < 128) {
        // ================= WORKER =================
        const int hc     = bid & 31;
        const int bg     = bid >> 5;
        const int h_base = hc * 8;
        const int b_base = bg * 32;

        float* xs    = (float*)(dsm + SM_XS);    // [dir*4224 + lb*132 + e]
        float* red   = (float*)(dsm + SM_RED);
        int*   tok_s = (int*)  (dsm + SM_TOK);
        const unsigned int sb   = smem_u32(dsm);
        const unsigned int mbar = sb + SM_MBAR;

        if (tid == 0)
            asm volatile("mbarrier.init.shared.b64 [%0], 1;" :: "r"(mbar) : "memory");
        if (tid < 64) {
            const int dir = tid >> 5;
            const int lb  = tid & 31;
            tok_s[tid] = inputs[(b_base + lb) * NB_S + (dir ? 0 : (NB_S - 1))];
        }
        __syncthreads();

        // 6 bulk copies: W tile rows (i,g,o per dir; f-gate skipped), 4 KB each.
        if (tid == 0) {
            asm volatile("mbarrier.arrive.expect_tx.shared.b64 _, [%0], %1;"
                         :: "r"(mbar), "r"(24576u) : "memory");
            const int goff[3] = {0, 512, 768};
            #pragma unroll
            for (int c = 0; c < 6; c++) {
                const float* src = (c >= 3 ? Wxb : Wxf)
                                 + (goff[c % 3] + h_base) * NB_EMB;
                const unsigned int dst = sb + SM_WSM + c * 4096;
                asm volatile(
                    "cp.async.bulk.shared::cluster.global.mbarrier::complete_tx::bytes "
                    "[%0], [%1], %2, [%3];"
                    :: "r"(dst), "l"(src), "r"(4096u), "r"(mbar) : "memory");
            }
        }

        // Gather embeddings into padded rows (overlaps DMA). float4 STS is CF
        // (lane word-stride 4 within each 8-lane phase).
        #pragma unroll
        for (int it = 0; it < 8; it++) {
            const int idx = tid + it * 256;          // 2048 float4 total
            const int e4  = idx & 31;
            const int lb  = (idx >> 5) & 31;
            const int dir = idx >> 10;
            const int tok = tok_s[dir * 32 + lb];
            const float4 v = ((const float4*)(weight + tok * NB_EMB))[e4];
            *(float4*)(xs + dir * 4224 + lb * 132 + e4 * 4) = v;
        }

        const int w   = tid >> 5;      // 8 warps
        const int lb  = tid & 31;      // lane = batch
        const int dir = w >> 2;        // 0 fwd / 1 bwd
        const int hp  = w & 3;         // h-pair index

        // Bias sums (warp-uniform; c=0 => bx + bh only). 3 gates x 2 h.
        const float* bx = dir ? bxb : bxf;
        const float* bh = dir ? bhb : bhf;
        float bias[6];
        #pragma unroll
        for (int g = 0; g < 3; g++) {
            const int go = (g == 0 ? 0 : (g == 1 ? 512 : 768));
            #pragma unroll
            for (int j = 0; j < 2; j++) {
                const int h = h_base + 2 * hp + j;
                bias[g * 2 + j] = bx[go + h] + bh[go + h];
            }
        }

        __syncthreads();      // xs ready
        mbar_wait0(mbar);     // W tile ready

        // GEMV: per k4 (4 k): 1 x LDS.128 (CF, stride 132) + 6 W LDS.128
        // (broadcast) + 12 FMA2.
        unsigned int wrow[6];
        #pragma unroll
        for (int g = 0; g < 3; g++)
            #pragma unroll
            for (int j = 0; j < 2; j++)
                wrow[g * 2 + j] = sb + SM_WSM
                                + (((dir * 3 + g) * 8) + 2 * hp + j) * 512;

        const unsigned int xaddr = sb + SM_XS + (dir * 4224 + lb * 132) * 4;

        unsigned long long acc[6] = {0ull, 0ull, 0ull, 0ull, 0ull, 0ull};
        #pragma unroll 8
        for (int k4 = 0; k4 < 32; k4++) {
            unsigned long long xa, xb;
            lds_v2b64(xaddr + k4 * 16, xa, xb);
            #pragma unroll
            for (int r = 0; r < 6; r++) {
                unsigned long long w01, w23;
                lds_v2b64(wrow[r] + k4 * 16, w01, w23);
                acc[r] = fma2(w01, xa, acc[r]);
                acc[r] = fma2(w23, xb, acc[r]);
            }
        }

        float hyv[2];
        #pragma unroll
        for (int j = 0; j < 2; j++) {
            const float gi = acc_sum(acc[0 * 2 + j]) + bias[0 * 2 + j];
            const float gg = acc_sum(acc[1 * 2 + j]) + bias[1 * 2 + j];
            const float go = acc_sum(acc[2 * 2 + j]) + bias[2 * 2 + j];
            hyv[j] = fsigm(go) * ftanh(fsigm(gi) * ftanh(gg));
        }

        __syncthreads();
        if (dir == 1) {
            red[(2 * hp + 0) * 33 + lb] = hyv[0];
            red[(2 * hp + 1) * 33 + lb] = hyv[1];
        }
        __syncthreads();
        if (dir == 0) {
            #pragma unroll
            for (int j = 0; j < 2; j++) {
                const int hl = 2 * hp + j;
                g_hy[(h_base + hl) * NB_B + b_base + lb] =
                    hyv[j] + red[hl * 33 + lb];
            }
        }

        __syncthreads();
        if (tid == 0) {
            __threadfence();
            atomicAdd(&g_wcnt[bg], 1u);
        }
    } else {
        // ================= HEAD (16 blocks, 8 batches each) =================
        const int hb = bid - 128;        // 0..15
        const int bg = hb >> 2;
        const int q  = hb & 3;
        const int b0 = bg * 32 + q * 8;

        float* Why_s = (float*)(dsm + SM_XS);    // [o*260 + k]  (CF LDS.128)
        float* hy_s  = (float*)(dsm + SM_WSM);   // [bl*260 + k] (broadcast)

        // Stage Why during the worker phase.
        #pragma unroll
        for (int it = 0; it < 32; it++) {
            const int idx = tid + it * 256;      // 8192
            const int o = idx >> 8;
            const int k = idx & 255;
            Why_s[o * 260 + k] = Why[idx];
        }

        // Epoch-safe wait: N = hcnt/4 (this block hasn't incremented yet);
        // wait until wcnt >= 32*(N+1).
        if (tid == 0) {
            unsigned int h0;
            asm volatile("ld.global.relaxed.gpu.u32 %0, [%1];"
                         : "=r"(h0) : "l"(&g_hcnt[bg]));
            const unsigned int target = ((h0 >> 2) + 1u) * 32u;
            unsigned int v;
            do {
                asm volatile("ld.global.acquire.gpu.u32 %0, [%1];"
                             : "=r"(v) : "l"(&g_wcnt[bg]) : "memory");
                if ((int)(v - target) >= 0) break;
                __nanosleep(32);
            } while (true);
        }
        __syncthreads();

        // Stage hy for 8 batches (2048 floats). STS CF via 260-word rows.
        #pragma unroll
        for (int it = 0; it < 8; it++) {
            const int idx = tid + it * 256;
            const int bl  = idx & 7;
            const int k   = idx >> 3;
            hy_s[bl * 260 + k] = g_hy[k * NB_B + b0 + bl];
        }
        __syncthreads();

        // warp = batch, lane = output o. Vectorized: per k4 one broadcast
        // hy LDS.128 + one CF Why LDS.128 + 4 FMA.
        const int o  = tid & 31;
        const int bl = tid >> 5;
        const float4* hy4 = (const float4*)(hy_s + bl * 260);
        const float4* wy4 = (const float4*)(Why_s + o * 260);

        float a0 = 0.f, a1 = 0.f, a2 = 0.f, a3 = 0.f;
        #pragma unroll 8
        for (int k4 = 0; k4 < 64; k4++) {
            const float4 hv = hy4[k4];
            const float4 wv = wy4[k4];
            a0 = fmaf(hv.x, wv.x, a0);
            a1 = fmaf(hv.y, wv.y, a1);
            a2 = fmaf(hv.z, wv.z, a2);
            a3 = fmaf(hv.w, wv.w, a3);
        }
        const float acc = ((a0 + a1) + (a2 + a3)) + by[o];

        float mx = acc;
        #pragma unroll
        for (int off = 16; off; off >>= 1)
            mx = fmaxf(mx, __shfl_xor_sync(0xffffffffu, mx, off));
        float s = __expf(acc - mx);
        #pragma unroll
        for (int off = 16; off; off >>= 1)
            s += __shfl_xor_sync(0xffffffffu, s, off);
        out[(b0 + bl) * NB_OUT + o] = acc - mx - __logf(s);

        __syncthreads();
        if (tid == 0) atomicAdd(&g_hcnt[bg], 1u);
    }
}

// Inputs in metadata order:
// 0 inputs(int32) 1 weight 2 Wxf 3 bxf 4 Whf(unused) 5 bhf
// 6 Wxb 7 bxb 8 Whb(unused) 9 bhb 10 Why 11 by
extern "C" void kernel_launch(void* const* d_in, const int* in_sizes, int n_in,
                              void* d_out, int out_size)
{
    const int*   inputs = (const int*)  d_in[0];
    const float* weight = (const float*)d_in[1];
    const float* Wxf    = (const float*)d_in[2];
    const float* bxf    = (const float*)d_in[3];
    const float* bhf    = (const float*)d_in[5];
    const float* Wxb    = (const float*)d_in[6];
    const float* bxb    = (const float*)d_in[7];
    const float* bhb    = (const float*)d_in[9];
    const float* Why    = (const float*)d_in[10];
    const float* by     = (const float*)d_in[11];
    float*       out    = (float*)d_out;

    static int configured = 0;
    if (!configured) {
        cudaFuncSetAttribute(bilstm_kernel,
                             cudaFuncAttributeMaxDynamicSharedMemorySize,
                             SMEM_BYTES);
        configured = 1;
    }

    bilstm_kernel<<<144, 256, SMEM_BYTES>>>(inputs, weight, Wxf, bxf, bhf,
                                            Wxb, bxb, bhb, Why, by, out);
}